// round 5
// baseline (speedup 1.0000x reference)
#include <cuda_runtime.h>
#include <cub/cub.cuh>

// Defeat --use_fast_math's expf -> __expf macro so expf = accurate libdevice
// __nv_expf, matching XLA's f32 exp bit-for-bit.
#ifdef expf
#undef expf
#endif

#define NB      4        // batch
#define NP      34125    // priors
#define NSEL    5000     // NMS_TOP_K
#define TOPK    750
#define NW      79       // ceil(NSEL/64)
#define CONF_T  0.05f
#define NMS_T   0.3f
#define NT      1024     // NMS block threads

// dynamic smem: 6 float arrays of NSEL + rowmask[64] + supp[NW] (u64)
#define SMEM_BYTES (6 * NSEL * 4 + 64 * 8 + NW * 8)

// ---------------- static device scratch (no allocations allowed) ------------
__device__ unsigned long long g_keys_in [NB * NP];
__device__ unsigned int       g_vals_in [NB * NP];
__device__ unsigned long long g_keys_out[NB * NP];
__device__ unsigned int       g_vals_out[NB * NP];
__device__ unsigned char      g_temp[1u << 24];   // cub temp, 16 MB

// ---------------- helpers ----------------------------------------------------

__device__ __forceinline__ unsigned int f2sortable(float f) {
    unsigned int b = __float_as_uint(f);
    return (b & 0x80000000u) ? ~b : (b | 0x80000000u);
}
__device__ __forceinline__ float sortable2f(unsigned int u) {
    return __uint_as_float((u & 0x80000000u) ? (u & 0x7fffffffu) : ~u);
}

// ---------------- kernels ----------------------------------------------------

// 64-bit composite keys: high bits = (3-img) so descending sort groups img 0
// first; low 32 bits = monotonic map of thresholded score. Stable radix sort
// preserves ascending-index order among ties == jax.lax.top_k tie-breaking.
__global__ void k_build(const float* __restrict__ conf) {
    int i = blockIdx.x * blockDim.x + threadIdx.x;
    if (i >= NB * NP) return;
    float c = conf[2 * i + 1];                 // class-1 score
    float s = (c > CONF_T) ? c : -1e30f;
    int img = i / NP;
    g_keys_in[i] = ((unsigned long long)(3 - img) << 32) | (unsigned long long)f2sortable(s);
    g_vals_in[i] = (unsigned int)(i % NP);
}

// One block per image: fused decode + chunked greedy NMS + output.
// Exactly reproduces the reference sequential scan: candidate i's keep
// decision depends only on kept boxes with index < i, so processing 64-wide
// chunks in order (with cross-chunk suppression applied between chunks, and
// an in-register sequential greedy within the chunk) is equivalent.
__global__ __launch_bounds__(NT, 1)
void k_nms(const float* __restrict__ loc,
           const float* __restrict__ prior,
           float* __restrict__ out) {
    extern __shared__ float sm[];
    float* sx1 = sm;
    float* sy1 = sm + NSEL;
    float* sx2 = sm + 2 * NSEL;
    float* sy2 = sm + 3 * NSEL;
    float* sar = sm + 4 * NSEL;
    float* ssc = sm + 5 * NSEL;
    unsigned long long* rowmask = (unsigned long long*)(sm + 6 * NSEL); // [64]
    unsigned long long* supp    = rowmask + 64;                         // [NW]
    __shared__ unsigned long long s_kept;
    __shared__ int s_cnt;

    const int img = blockIdx.x;
    const int t   = threadIdx.x;

    // zero this image's two output pages (class 0 stays all-zero)
    float* page = out + (size_t)img * 2 * TOPK * 5;
    for (int i = t; i < 2 * TOPK * 5; i += NT) page[i] = 0.0f;

    // suppression bitmap: zero, tail bits j>=NSEL pre-set
    for (int w = t; w < NW; w += NT) {
        unsigned long long m = 0ull;
        int b0 = w * 64;
        if (b0 + 64 > NSEL)
            for (int b = 0; b < 64; b++)
                if (b0 + b >= NSEL) m |= (1ull << b);
        supp[w] = m;
    }
    __syncthreads();

    // fused gather + decode of the top-NSEL candidates into smem
    for (int j = t; j < NSEL; j += NT) {
        unsigned long long key = g_keys_out[img * NP + j];
        unsigned int p = g_vals_out[img * NP + j];
        float sc = sortable2f((unsigned int)key);

        const float* l  = loc   + ((size_t)img * NP + p) * 4;
        const float* pr = prior + (size_t)p * 4;
        float lx = l[0],  ly = l[1],  lw = l[2],  lh = l[3];
        float px = pr[0], py = pr[1], pw = pr[2], ph = pr[3];
        float cx = __fadd_rn(px, __fmul_rn(__fmul_rn(lx, 0.1f), pw));
        float cy = __fadd_rn(py, __fmul_rn(__fmul_rn(ly, 0.1f), ph));
        float w  = __fmul_rn(pw, expf(__fmul_rn(lw, 0.2f)));
        float h  = __fmul_rn(ph, expf(__fmul_rn(lh, 0.2f)));
        float x1 = __fsub_rn(cx, __fmul_rn(w, 0.5f));
        float y1 = __fsub_rn(cy, __fmul_rn(h, 0.5f));
        float x2 = __fadd_rn(x1, w);
        float y2 = __fadd_rn(y1, h);

        sx1[j] = x1; sy1[j] = y1; sx2[j] = x2; sy2[j] = y2;
        sar[j] = __fmul_rn(__fsub_rn(x2, x1), __fsub_rn(y2, y1));
        ssc[j] = sc;
        if (!(sc > CONF_T))   // sorted desc -> never kept, never suppresses
            atomicOr(&supp[j >> 6], 1ull << (j & 63));
    }
    __syncthreads();

    int rank = 0;
    for (int c = 0; c < NW; c++) {
        const int base = c * 64;
        const unsigned long long in_sup = supp[c];   // stable: uniform read
        if (in_sup == ~0ull) continue;               // uniform branch

        // (a) intra-chunk IoU bitmask rows (threads 0..63)
        if (t < 64) {
            unsigned long long bits = 0ull;
            int i = base + t;
            if (i < NSEL && !((in_sup >> t) & 1ull)) {
                float ix1 = sx1[i], iy1 = sy1[i], ix2 = sx2[i], iy2 = sy2[i];
                float ia  = sar[i];
                for (int b = t + 1; b < 64; b++) {
                    int j = base + b;
                    if (j >= NSEL) break;
                    if ((in_sup >> b) & 1ull) continue;
                    float iw = fmaxf(__fsub_rn(fminf(ix2, sx2[j]), fmaxf(ix1, sx1[j])), 0.0f);
                    float ih = fmaxf(__fsub_rn(fminf(iy2, sy2[j]), fmaxf(iy1, sy1[j])), 0.0f);
                    float inter = __fmul_rn(iw, ih);
                    float den   = __fsub_rn(__fadd_rn(ia, sar[j]), inter);
                    float iou   = __fdiv_rn(inter, den);
                    if (iou > NMS_T) bits |= (1ull << b);
                }
            }
            rowmask[t] = bits;
        }
        __syncthreads();

        // (b) 64-step local greedy, one thread, registers only
        if (t == 0) {
            unsigned long long kept = 0ull;
            unsigned long long avail = ~in_sup;
            int cnt = 0, room = TOPK - rank;
            while (avail && cnt < room) {
                int b = __ffsll((long long)avail) - 1;
                kept |= (1ull << b);
                cnt++;
                avail &= ~rowmask[b];
                avail &= ~(1ull << b);
            }
            s_kept = kept;
            s_cnt  = cnt;
        }
        __syncthreads();

        const unsigned long long kept = s_kept;
        const int cnt = s_cnt;

        // write output rows for newly-kept boxes
        if (t < 64 && ((kept >> t) & 1ull)) {
            int r = rank + __popcll(kept & ((1ull << t) - 1ull));
            int i = base + t;
            float* row = out + (((size_t)(img * 2 + 1)) * TOPK + r) * 5;
            row[0] = ssc[i];
            row[1] = sx1[i]; row[2] = sy1[i]; row[3] = sx2[i]; row[4] = sy2[i];
        }
        rank += cnt;
        if (rank >= TOPK) break;   // uniform

        // (c) parallel suppression of all later candidates vs newly-kept boxes
        if (kept) {
            for (int j = base + 64 + t; j < NSEL; j += NT) {
                int w = j >> 6;
                if ((supp[w] >> (j & 63)) & 1ull) continue;
                float jx1 = sx1[j], jy1 = sy1[j], jx2 = sx2[j], jy2 = sy2[j];
                float ja  = sar[j];
                unsigned long long km = kept;
                bool dead = false;
                while (km) {
                    int b = __ffsll((long long)km) - 1;
                    km &= km - 1ull;
                    int i = base + b;
                    float iw = fmaxf(__fsub_rn(fminf(sx2[i], jx2), fmaxf(sx1[i], jx1)), 0.0f);
                    float ih = fmaxf(__fsub_rn(fminf(sy2[i], jy2), fmaxf(sy1[i], jy1)), 0.0f);
                    float inter = __fmul_rn(iw, ih);
                    float den   = __fsub_rn(__fadd_rn(sar[i], ja), inter);
                    float iou   = __fdiv_rn(inter, den);
                    if (iou > NMS_T) { dead = true; break; }
                }
                if (dead) atomicOr(&supp[w], 1ull << (j & 63));
            }
        }
        __syncthreads();
    }
}

// ---------------- launch ------------------------------------------------------

extern "C" void kernel_launch(void* const* d_in, const int* in_sizes, int n_in,
                              void* d_out, int out_size) {
    const float* loc   = (const float*)d_in[0];
    const float* conf  = (const float*)d_in[1];
    const float* prior = (const float*)d_in[2];
    float* out = (float*)d_out;

    void *keys_in_p, *vals_in_p, *keys_out_p, *vals_out_p, *temp_p;
    cudaGetSymbolAddress(&keys_in_p,  g_keys_in);
    cudaGetSymbolAddress(&vals_in_p,  g_vals_in);
    cudaGetSymbolAddress(&keys_out_p, g_keys_out);
    cudaGetSymbolAddress(&vals_out_p, g_vals_out);
    cudaGetSymbolAddress(&temp_p,     g_temp);

    cudaFuncSetAttribute(k_nms, cudaFuncAttributeMaxDynamicSharedMemorySize,
                         SMEM_BYTES);

    k_build<<<(NB * NP + 255) / 256, 256>>>(conf);

    size_t tmp_bytes = 0;
    cub::DeviceRadixSort::SortPairsDescending(
        nullptr, tmp_bytes,
        (const unsigned long long*)keys_in_p, (unsigned long long*)keys_out_p,
        (const unsigned int*)vals_in_p,       (unsigned int*)vals_out_p,
        NB * NP, 0, 34, (cudaStream_t)0);
    if (tmp_bytes > (size_t)(1u << 24)) tmp_bytes = (size_t)(1u << 24);
    cub::DeviceRadixSort::SortPairsDescending(
        temp_p, tmp_bytes,
        (const unsigned long long*)keys_in_p, (unsigned long long*)keys_out_p,
        (const unsigned int*)vals_in_p,       (unsigned int*)vals_out_p,
        NB * NP, 0, 34, (cudaStream_t)0);

    k_nms<<<NB, NT, SMEM_BYTES>>>(loc, prior, out);
}

// round 6
// speedup vs baseline: 2.1753x; 2.1753x over previous
#include <cuda_runtime.h>
#include <cub/cub.cuh>

// Defeat --use_fast_math's expf -> __expf macro so expf = accurate libdevice
// __nv_expf, matching XLA's f32 exp bit-for-bit.
#ifdef expf
#undef expf
#endif

#define NB      4        // batch
#define NP      34125    // priors
#define NSEL    5000     // NMS_TOP_K
#define TOPK    750
#define NW      79       // ceil(NSEL/64)
#define CONF_T  0.05f
#define NMS_T   0.3f
#define NT2     256      // reduce block threads

// ---------------- static device scratch (no allocations allowed) ------------
__device__ unsigned long long g_keys_in [NB * NP];
__device__ unsigned int       g_vals_in [NB * NP];
__device__ unsigned long long g_keys_out[NB * NP];
__device__ unsigned int       g_vals_out[NB * NP];

__device__ float g_bx1[NB * NSEL];
__device__ float g_by1[NB * NSEL];
__device__ float g_bx2[NB * NSEL];
__device__ float g_by2[NB * NSEL];
__device__ float g_sc [NB * NSEL];

__device__ unsigned long long g_mask[(size_t)NB * NSEL * NW]; // ~12.6 MB (L2-resident)
__device__ unsigned char      g_temp[1u << 24];               // cub temp, 16 MB

// ---------------- helpers ----------------------------------------------------

__device__ __forceinline__ unsigned int f2sortable(float f) {
    unsigned int b = __float_as_uint(f);
    return (b & 0x80000000u) ? ~b : (b | 0x80000000u);
}
__device__ __forceinline__ float sortable2f(unsigned int u) {
    return __uint_as_float((u & 0x80000000u) ? (u & 0x7fffffffu) : ~u);
}

// ---------------- kernels ----------------------------------------------------

// 64-bit composite keys: high bits = (3-img) so one descending onesweep sort
// orders img 0 first; low 32 = monotonic map of thresholded score. Stable
// radix sort keeps ascending-index tie order == jax.lax.top_k.
__global__ void k_build(const float* __restrict__ conf) {
    int i = blockIdx.x * blockDim.x + threadIdx.x;
    if (i >= NB * NP) return;
    float c = conf[2 * i + 1];                 // class-1 score
    float s = (c > CONF_T) ? c : -1e30f;
    int img = i / NP;
    g_keys_in[i] = ((unsigned long long)(3 - img) << 32) | (unsigned long long)f2sortable(s);
    g_vals_in[i] = (unsigned int)(i % NP);
}

__global__ void k_gather(const float* __restrict__ loc,
                         const float* __restrict__ prior) {
    int t = blockIdx.x * blockDim.x + threadIdx.x;
    if (t >= NB * NSEL) return;
    int img = t / NSEL, j = t % NSEL;
    unsigned long long key = g_keys_out[img * NP + j];
    unsigned int p = g_vals_out[img * NP + j];
    g_sc[t] = sortable2f((unsigned int)key);

    const float* l  = loc   + ((size_t)img * NP + p) * 4;
    const float* pr = prior + (size_t)p * 4;
    float lx = l[0],  ly = l[1],  lw = l[2],  lh = l[3];
    float px = pr[0], py = pr[1], pw = pr[2], ph = pr[3];

    float cx = __fadd_rn(px, __fmul_rn(__fmul_rn(lx, 0.1f), pw));
    float cy = __fadd_rn(py, __fmul_rn(__fmul_rn(ly, 0.1f), ph));
    float w  = __fmul_rn(pw, expf(__fmul_rn(lw, 0.2f)));
    float h  = __fmul_rn(ph, expf(__fmul_rn(lh, 0.2f)));
    float x1 = __fsub_rn(cx, __fmul_rn(w, 0.5f));
    float y1 = __fsub_rn(cy, __fmul_rn(h, 0.5f));
    float x2 = __fadd_rn(x1, w);
    float y2 = __fadd_rn(y1, h);
    g_bx1[t] = x1; g_by1[t] = y1; g_bx2[t] = x2; g_by2[t] = y2;
}

// Upper-triangular tiled IoU bitmask (grid-wide, embarrassingly parallel).
// block = 64 threads (one row each); blockIdx = (col tile, row tile, image).
__global__ void k_mask() {
    int bx = blockIdx.x, by = blockIdx.y, img = blockIdx.z;
    if (bx < by) return;   // only words w >= i>>6 are ever read downstream
    __shared__ float sx1[64], sy1[64], sx2[64], sy2[64], sa[64];
    int t  = threadIdx.x;
    int j0 = bx * 64;
    int jj = j0 + t;
    if (jj < NSEL) {
        int o = img * NSEL + jj;
        float x1 = g_bx1[o], y1 = g_by1[o], x2 = g_bx2[o], y2 = g_by2[o];
        sx1[t] = x1; sy1[t] = y1; sx2[t] = x2; sy2[t] = y2;
        sa[t] = __fmul_rn(__fsub_rn(x2, x1), __fsub_rn(y2, y1));
    }
    __syncthreads();
    int i = by * 64 + t;
    if (i >= NSEL) return;
    int oi = img * NSEL + i;
    float ix1 = g_bx1[oi], iy1 = g_by1[oi], ix2 = g_bx2[oi], iy2 = g_by2[oi];
    float ia  = __fmul_rn(__fsub_rn(ix2, ix1), __fsub_rn(iy2, iy1));
    int cnt = min(64, NSEL - j0);
    unsigned long long bits = 0ull;
#pragma unroll 4
    for (int c = 0; c < cnt; c++) {
        int j = j0 + c;
        if (j <= i) continue;
        float iw = fmaxf(__fsub_rn(fminf(ix2, sx2[c]), fmaxf(ix1, sx1[c])), 0.0f);
        float ih = fmaxf(__fsub_rn(fminf(iy2, sy2[c]), fmaxf(iy1, sy1[c])), 0.0f);
        float inter = __fmul_rn(iw, ih);
        float den   = __fsub_rn(__fadd_rn(ia, sa[c]), inter);
        float iou   = __fdiv_rn(inter, den);
        if (iou > NMS_T) bits |= (1ull << c);
    }
    g_mask[((size_t)img * NSEL + i) * NW + bx] = bits;
}

// One block per image: chunked greedy reduce over the precomputed bitmask.
// Serial work per chunk is tiny (cnt-step register greedy); suppression is
// pure bitmap OR across threads (no IoU recompute, no atomics).
__global__ __launch_bounds__(NT2, 1)
void k_reduce(float* __restrict__ out) {
    __shared__ unsigned long long remv[NW];
    __shared__ unsigned long long rowm[64];
    __shared__ int keptlist[64];
    __shared__ unsigned long long s_kept;
    __shared__ int s_cnt;

    const int img = blockIdx.x;
    const int t   = threadIdx.x;
    const unsigned long long* mbase = g_mask + (size_t)img * NSEL * NW;

    // zero this image's two output pages (class 0 stays all-zero)
    float* page = out + (size_t)img * 2 * TOPK * 5;
    for (int i = t; i < 2 * TOPK * 5; i += NT2) page[i] = 0.0f;

    // suppression bitmap: tail bits preset
    for (int w = t; w < NW; w += NT2) {
        unsigned long long m = 0ull;
        int b0 = w * 64;
        if (b0 + 64 > NSEL)
            for (int b = 0; b < 64; b++)
                if (b0 + b >= NSEL) m |= (1ull << b);
        remv[w] = m;
    }
    __syncthreads();
    // invalid candidates (score <= thresh): never kept, never suppress
    for (int j = t; j < NSEL; j += NT2)
        if (!(g_sc[img * NSEL + j] > CONF_T))
            atomicOr(&remv[j >> 6], 1ull << (j & 63));
    __syncthreads();

    int rank = 0;
    for (int c = 0; c < NW; c++) {
        const unsigned long long dead = remv[c];   // uniform
        if (dead == ~0ull) continue;               // uniform branch
        const int base = c * 64;

        // (a) parallel load of the chunk's intra-chunk mask words
        if (t < 64) {
            rowm[t] = (base + t < NSEL) ? mbase[(size_t)(base + t) * NW + c] : 0ull;
        }
        __syncthreads();

        // (b) local greedy: cnt iterations, registers + LDS only
        if (t == 0) {
            unsigned long long kept = 0ull;
            unsigned long long avail = ~dead;
            int cnt = 0, room = TOPK - rank;
            while (avail && cnt < room) {
                int b = __ffsll((long long)avail) - 1;
                kept |= (1ull << b);
                keptlist[cnt++] = b;
                avail &= ~rowm[b];
                avail &= ~(1ull << b);
            }
            s_kept = kept;
            s_cnt  = cnt;
        }
        __syncthreads();

        const unsigned long long kept = s_kept;
        const int cnt = s_cnt;

        // output rows for newly-kept boxes
        if (t < 64 && ((kept >> t) & 1ull)) {
            int r = rank + __popcll(kept & ((1ull << t) - 1ull));
            int i = base + t;
            int o = img * NSEL + i;
            float* row = out + (((size_t)(img * 2 + 1)) * TOPK + r) * 5;
            row[0] = g_sc[o];
            row[1] = g_bx1[o]; row[2] = g_by1[o];
            row[3] = g_bx2[o]; row[4] = g_by2[o];
        }
        rank += cnt;
        if (rank >= TOPK) break;   // uniform

        // (c) suppress later chunks: one thread per word, cnt independent
        // L2 loads (MLP-covered), single writer per word -> no atomics
        if (kept) {
            for (int w = c + 1 + t; w < NW; w += NT2) {
                unsigned long long acc = 0ull;
#pragma unroll 4
                for (int k = 0; k < cnt; k++)
                    acc |= mbase[(size_t)(base + keptlist[k]) * NW + w];
                remv[w] |= acc;
            }
        }
        __syncthreads();
    }
}

// ---------------- launch ------------------------------------------------------

extern "C" void kernel_launch(void* const* d_in, const int* in_sizes, int n_in,
                              void* d_out, int out_size) {
    const float* loc   = (const float*)d_in[0];
    const float* conf  = (const float*)d_in[1];
    const float* prior = (const float*)d_in[2];
    float* out = (float*)d_out;

    void *keys_in_p, *vals_in_p, *keys_out_p, *vals_out_p, *temp_p;
    cudaGetSymbolAddress(&keys_in_p,  g_keys_in);
    cudaGetSymbolAddress(&vals_in_p,  g_vals_in);
    cudaGetSymbolAddress(&keys_out_p, g_keys_out);
    cudaGetSymbolAddress(&vals_out_p, g_vals_out);
    cudaGetSymbolAddress(&temp_p,     g_temp);

    k_build<<<(NB * NP + 255) / 256, 256>>>(conf);

    size_t tmp_bytes = 0;
    cub::DeviceRadixSort::SortPairsDescending(
        nullptr, tmp_bytes,
        (const unsigned long long*)keys_in_p, (unsigned long long*)keys_out_p,
        (const unsigned int*)vals_in_p,       (unsigned int*)vals_out_p,
        NB * NP, 0, 34, (cudaStream_t)0);
    if (tmp_bytes > (size_t)(1u << 24)) tmp_bytes = (size_t)(1u << 24);
    cub::DeviceRadixSort::SortPairsDescending(
        temp_p, tmp_bytes,
        (const unsigned long long*)keys_in_p, (unsigned long long*)keys_out_p,
        (const unsigned int*)vals_in_p,       (unsigned int*)vals_out_p,
        NB * NP, 0, 34, (cudaStream_t)0);

    k_gather<<<(NB * NSEL + 255) / 256, 256>>>(loc, prior);

    dim3 mg(NW, NW, NB);
    k_mask<<<mg, 64>>>();

    k_reduce<<<NB, NT2>>>(out);
}

// round 7
// speedup vs baseline: 3.1308x; 1.4393x over previous
#include <cuda_runtime.h>
#include <cub/cub.cuh>

// Defeat --use_fast_math's expf -> __expf macro so expf = accurate libdevice
// __nv_expf, matching XLA's f32 exp bit-for-bit.
#ifdef expf
#undef expf
#endif

#define NB      4        // batch
#define NP      34125    // priors
#define NSEL    5000     // NMS_TOP_K
#define TOPK    750
#define NW      79       // ceil(NSEL/64)
#define CONF_T  0.05f
#define NMS_T   0.3f
#define NT2     256      // reduce block threads
#define NCH     20       // ceil(NSEL/256) chunks of 256 candidates

// ---------------- static device scratch (no allocations allowed) ------------
__device__ unsigned long long g_keys_in [NB * NP];
__device__ unsigned int       g_vals_in [NB * NP];
__device__ unsigned long long g_keys_out[NB * NP];
__device__ unsigned int       g_vals_out[NB * NP];

__device__ float g_bx1[NB * NSEL];
__device__ float g_by1[NB * NSEL];
__device__ float g_bx2[NB * NSEL];
__device__ float g_by2[NB * NSEL];
__device__ float g_sc [NB * NSEL];

__device__ unsigned long long g_mask[(size_t)NB * NSEL * NW]; // ~12.6 MB (L2-resident)
__device__ unsigned char      g_temp[1u << 24];               // cub temp, 16 MB

// ---------------- helpers ----------------------------------------------------

__device__ __forceinline__ unsigned int f2sortable(float f) {
    unsigned int b = __float_as_uint(f);
    return (b & 0x80000000u) ? ~b : (b | 0x80000000u);
}
__device__ __forceinline__ float sortable2f(unsigned int u) {
    return __uint_as_float((u & 0x80000000u) ? (u & 0x7fffffffu) : ~u);
}

// ---------------- kernels ----------------------------------------------------

// 64-bit composite keys: high bits = (3-img) so one descending onesweep sort
// orders img 0 first; low 32 = monotonic map of thresholded score. Stable
// radix sort keeps ascending-index tie order == jax.lax.top_k.
__global__ void k_build(const float* __restrict__ conf) {
    int i = blockIdx.x * blockDim.x + threadIdx.x;
    if (i >= NB * NP) return;
    float c = conf[2 * i + 1];                 // class-1 score
    float s = (c > CONF_T) ? c : -1e30f;
    int img = i / NP;
    g_keys_in[i] = ((unsigned long long)(3 - img) << 32) | (unsigned long long)f2sortable(s);
    g_vals_in[i] = (unsigned int)(i % NP);
}

__global__ void k_gather(const float* __restrict__ loc,
                         const float* __restrict__ prior) {
    int t = blockIdx.x * blockDim.x + threadIdx.x;
    if (t >= NB * NSEL) return;
    int img = t / NSEL, j = t % NSEL;
    unsigned long long key = g_keys_out[img * NP + j];
    unsigned int p = g_vals_out[img * NP + j];
    g_sc[t] = sortable2f((unsigned int)key);

    const float* l  = loc   + ((size_t)img * NP + p) * 4;
    const float* pr = prior + (size_t)p * 4;
    float lx = l[0],  ly = l[1],  lw = l[2],  lh = l[3];
    float px = pr[0], py = pr[1], pw = pr[2], ph = pr[3];

    float cx = __fadd_rn(px, __fmul_rn(__fmul_rn(lx, 0.1f), pw));
    float cy = __fadd_rn(py, __fmul_rn(__fmul_rn(ly, 0.1f), ph));
    float w  = __fmul_rn(pw, expf(__fmul_rn(lw, 0.2f)));
    float h  = __fmul_rn(ph, expf(__fmul_rn(lh, 0.2f)));
    float x1 = __fsub_rn(cx, __fmul_rn(w, 0.5f));
    float y1 = __fsub_rn(cy, __fmul_rn(h, 0.5f));
    float x2 = __fadd_rn(x1, w);
    float y2 = __fadd_rn(y1, h);
    g_bx1[t] = x1; g_by1[t] = y1; g_bx2[t] = x2; g_by2[t] = y2;
}

// Upper-triangular tiled IoU bitmask (grid-wide, embarrassingly parallel).
// block = 64 threads (one row each); blockIdx = (col tile, row tile, image).
__global__ void k_mask() {
    int bx = blockIdx.x, by = blockIdx.y, img = blockIdx.z;
    if (bx < by) return;   // only words w >= i>>6 are ever consulted downstream
    __shared__ float sx1[64], sy1[64], sx2[64], sy2[64], sa[64];
    int t  = threadIdx.x;
    int j0 = bx * 64;
    int jj = j0 + t;
    if (jj < NSEL) {
        int o = img * NSEL + jj;
        float x1 = g_bx1[o], y1 = g_by1[o], x2 = g_bx2[o], y2 = g_by2[o];
        sx1[t] = x1; sy1[t] = y1; sx2[t] = x2; sy2[t] = y2;
        sa[t] = __fmul_rn(__fsub_rn(x2, x1), __fsub_rn(y2, y1));
    }
    __syncthreads();
    int i = by * 64 + t;
    if (i >= NSEL) return;
    int oi = img * NSEL + i;
    float ix1 = g_bx1[oi], iy1 = g_by1[oi], ix2 = g_bx2[oi], iy2 = g_by2[oi];
    float ia  = __fmul_rn(__fsub_rn(ix2, ix1), __fsub_rn(iy2, iy1));
    int cnt = min(64, NSEL - j0);
    unsigned long long bits = 0ull;
#pragma unroll 4
    for (int c = 0; c < cnt; c++) {
        int j = j0 + c;
        if (j <= i) continue;
        float iw = fmaxf(__fsub_rn(fminf(ix2, sx2[c]), fmaxf(ix1, sx1[c])), 0.0f);
        float ih = fmaxf(__fsub_rn(fminf(iy2, sy2[c]), fmaxf(iy1, sy1[c])), 0.0f);
        float inter = __fmul_rn(iw, ih);
        float den   = __fsub_rn(__fadd_rn(ia, sa[c]), inter);
        float iou   = __fdiv_rn(inter, den);
        if (iou > NMS_T) bits |= (1ull << c);
    }
    g_mask[((size_t)img * NSEL + i) * NW + bx] = bits;
}

// One block per image: 256-wide chunked greedy reduce over the precomputed
// bitmask. 20 chunks => ~60 barriers + ~20 L2-latency windows on the serial
// path (vs 79/237 with 64-wide chunks). Suppression = pure bitmap OR.
__global__ __launch_bounds__(NT2, 1)
void k_reduce(float* __restrict__ out) {
    __shared__ unsigned long long remv[80];        // word 79 = pad (~0)
    __shared__ unsigned long long rowm[NT2 * 4];   // intra-chunk mask rows, 8KB
    __shared__ unsigned long long s_kept[4];
    __shared__ int s_cnt;
    __shared__ int keptlist[NT2];

    const int img = blockIdx.x;
    const int t   = threadIdx.x;
    const unsigned long long* mbase = g_mask + (size_t)img * NSEL * NW;

    // zero this image's two output pages (class 0 stays all-zero)
    float* page = out + (size_t)img * 2 * TOPK * 5;
    for (int i = t; i < 2 * TOPK * 5; i += NT2) page[i] = 0.0f;

    // suppression bitmap: tail bits (>= NSEL) preset; word 79 pad = all-ones
    for (int w = t; w < 80; w += NT2) {
        unsigned long long m = 0ull;
        int b0 = w * 64;
        if (b0 + 64 > NSEL) {
            for (int b = 0; b < 64; b++)
                if (b0 + b >= NSEL) m |= (1ull << b);
        }
        remv[w] = m;
    }
    __syncthreads();
    // invalid candidates (score <= thresh): never kept, never suppress
    for (int j = t; j < NSEL; j += NT2)
        if (!(g_sc[img * NSEL + j] > CONF_T))
            atomicOr(&remv[j >> 6], 1ull << (j & 63));
    __syncthreads();

    int rank = 0;
    for (int c = 0; c < NCH; c++) {
        const int w0   = c * 4;
        const int base = c * 256;
        if ((remv[w0] & remv[w0 + 1] & remv[w0 + 2] & remv[w0 + 3]) == ~0ull)
            continue;   // uniform skip

        // (a) load the chunk's 256x4-word intra-chunk mask block
        {
            int i = base + t;
            if (i < NSEL) {
                const unsigned long long* rp = mbase + (size_t)i * NW + w0;
#pragma unroll
                for (int k = 0; k < 4; k++)
                    rowm[t * 4 + k] = (w0 + k < NW) ? rp[k] : 0ull;
            } else {
#pragma unroll
                for (int k = 0; k < 4; k++) rowm[t * 4 + k] = 0ull;
            }
        }
        __syncthreads();

        // (b) local greedy on a 256-bit avail vector, one thread, regs+LDS
        if (t == 0) {
            unsigned long long av[4], kp[4] = {0ull, 0ull, 0ull, 0ull};
#pragma unroll
            for (int k = 0; k < 4; k++) av[k] = ~remv[w0 + k];
            int cnt = 0, room = TOPK - rank;
            while (cnt < room) {
                int ws;
                if      (av[0]) ws = 0;
                else if (av[1]) ws = 1;
                else if (av[2]) ws = 2;
                else if (av[3]) ws = 3;
                else break;
                int b   = __ffsll((long long)av[ws]) - 1;
                int loc = ws * 64 + b;
                kp[ws] |= (1ull << b);
                keptlist[cnt++] = loc;
                av[0] &= ~rowm[loc * 4 + 0];
                av[1] &= ~rowm[loc * 4 + 1];
                av[2] &= ~rowm[loc * 4 + 2];
                av[3] &= ~rowm[loc * 4 + 3];
                av[ws] &= ~(1ull << b);
            }
            s_kept[0] = kp[0]; s_kept[1] = kp[1];
            s_kept[2] = kp[2]; s_kept[3] = kp[3];
            s_cnt = cnt;
        }
        __syncthreads();

        const int cnt = s_cnt;

        // (c) output rows for newly-kept boxes (thread t owns local row t)
        {
            int wq = t >> 6, b = t & 63;
            if ((s_kept[wq] >> b) & 1ull) {
                int off = 0;
#pragma unroll
                for (int k = 0; k < 4; k++)
                    if (k < wq) off += __popcll(s_kept[k]);
                off += __popcll(s_kept[wq] & ((1ull << b) - 1ull));
                int r = rank + off;
                int o = img * NSEL + base + t;
                float* row = out + (((size_t)(img * 2 + 1)) * TOPK + r) * 5;
                row[0] = g_sc[o];
                row[1] = g_bx1[o]; row[2] = g_by1[o];
                row[3] = g_bx2[o]; row[4] = g_by2[o];
            }
        }
        rank += cnt;
        if (rank >= TOPK) break;   // uniform

        // (d) suppress later chunks: one thread per word, cnt independent
        // L2 loads (MLP-covered), single writer per word -> no atomics
        if (cnt > 0) {
            for (int w = w0 + 4 + t; w < NW; w += NT2) {
                unsigned long long acc = 0ull;
#pragma unroll 4
                for (int k = 0; k < cnt; k++)
                    acc |= mbase[(size_t)(base + keptlist[k]) * NW + w];
                remv[w] |= acc;
            }
        }
        __syncthreads();
    }
}

// ---------------- launch ------------------------------------------------------

extern "C" void kernel_launch(void* const* d_in, const int* in_sizes, int n_in,
                              void* d_out, int out_size) {
    const float* loc   = (const float*)d_in[0];
    const float* conf  = (const float*)d_in[1];
    const float* prior = (const float*)d_in[2];
    float* out = (float*)d_out;

    void *keys_in_p, *vals_in_p, *keys_out_p, *vals_out_p, *temp_p;
    cudaGetSymbolAddress(&keys_in_p,  g_keys_in);
    cudaGetSymbolAddress(&vals_in_p,  g_vals_in);
    cudaGetSymbolAddress(&keys_out_p, g_keys_out);
    cudaGetSymbolAddress(&vals_out_p, g_vals_out);
    cudaGetSymbolAddress(&temp_p,     g_temp);

    k_build<<<(NB * NP + 255) / 256, 256>>>(conf);

    size_t tmp_bytes = 0;
    cub::DeviceRadixSort::SortPairsDescending(
        nullptr, tmp_bytes,
        (const unsigned long long*)keys_in_p, (unsigned long long*)keys_out_p,
        (const unsigned int*)vals_in_p,       (unsigned int*)vals_out_p,
        NB * NP, 0, 34, (cudaStream_t)0);
    if (tmp_bytes > (size_t)(1u << 24)) tmp_bytes = (size_t)(1u << 24);
    cub::DeviceRadixSort::SortPairsDescending(
        temp_p, tmp_bytes,
        (const unsigned long long*)keys_in_p, (unsigned long long*)keys_out_p,
        (const unsigned int*)vals_in_p,       (unsigned int*)vals_out_p,
        NB * NP, 0, 34, (cudaStream_t)0);

    k_gather<<<(NB * NSEL + 255) / 256, 256>>>(loc, prior);

    dim3 mg(NW, NW, NB);
    k_mask<<<mg, 64>>>();

    k_reduce<<<NB, NT2>>>(out);
}